// round 2
// baseline (speedup 1.0000x reference)
#include <cuda_runtime.h>
#include <math.h>

// Problem constants
#define HW    4096
#define Bn    8
#define Tn    50
#define CIN   32

// Scratch (static __device__ arrays — allocation-free per harness rules)
__device__ float g_XC[400u * 128u * 4096u];   // [t*8+b][128][4096]  x-conv precompute (839 MB)
__device__ float g_yconv[8 * 96 * 4096];       // per-step conv(Y, Wy)
__device__ float g_Y[8 * 32 * 4096];
__device__ float g_Z[8 * 32 * 4096];
__device__ float g_G2[8 * 32 * 4096];          // sigmoid(xg2 + yg2) for current step

__device__ __forceinline__ float fsigmoid(float x) {
    return 1.0f / (1.0f + __expf(-x));
}
__device__ __forceinline__ float ftanh(float x) {
    x = fminf(fmaxf(x, -12.0f), 12.0f);
    float e = __expf(2.0f * x);
    return 1.0f - 2.0f / (e + 1.0f);
}

// ---------------------------------------------------------------------------
// Generic 3x3 SAME conv, Cin=32, CO_BLK=8 output channels per block.
// Block: 128 threads = 64 spatial threads (8x8, each a 4x4 patch => 32x32 tile)
//        x 2 channel subgroups (4 channels each). 64 fp32 accumulators/thread.
// MODE 0: in = X (all t,b images), out -> g_XC          (grid.z = 400)
// MODE 1: in = g_Y,               out -> g_yconv        (grid.z = 8)
// MODE 2: in = g_Z,  epilogue fuses Y update + output store (grid.z = 8)
// ---------------------------------------------------------------------------
template<int MODE>
__global__ void __launch_bounds__(128)
conv3x3_k(const float* __restrict__ xin,
          const float* __restrict__ wts,
          const float* __restrict__ bias,
          float* __restrict__ out,
          int t)
{
    __shared__ float sIn[8][34 * 34];   // 8 input channels of the (32+2)^2 halo tile
    __shared__ float sW[8][8][9];       // [ci][co][tap]

    const int tid  = threadIdx.x;
    const int tile = blockIdx.x;               // 0..3
    const int h0   = (tile >> 1) * 32;
    const int w0   = (tile & 1) * 32;
    const int cog  = blockIdx.y;               // output channel group (8 ch)
    const int img  = blockIdx.z;

    int b, ti;
    if (MODE == 0) { b = img & 7; ti = img >> 3; }
    else           { b = img;     ti = t; }

    size_t in_base; int chs;
    const float* src;
    if (MODE == 0) { src = xin;  in_base = ((size_t)b * CIN * Tn + ti) * HW; chs = Tn * HW; }
    else if (MODE == 1) { src = g_Y; in_base = (size_t)b * CIN * HW; chs = HW; }
    else { src = g_Z; in_base = (size_t)b * CIN * HW; chs = HW; }

    const int sp    = tid & 63;
    const int cosub = tid >> 6;               // 0 or 1
    const int py    = (sp >> 3) << 2;          // patch origin y in [0,32)
    const int px    = (sp & 7) << 2;           // patch origin x in [0,32)

    float acc[4][16];
#pragma unroll
    for (int i = 0; i < 4; i++)
#pragma unroll
        for (int j = 0; j < 16; j++) acc[i][j] = 0.0f;

    for (int ci0 = 0; ci0 < CIN; ci0 += 8) {
        // --- stage input halo tile (zero-padded SAME borders) ---
        for (int e = tid; e < 8 * 34 * 34; e += 128) {
            int ci = e / (34 * 34);
            int r  = e - ci * (34 * 34);
            int y  = r / 34;
            int x  = r - y * 34;
            int gy = h0 - 1 + y;
            int gx = w0 - 1 + x;
            float v = 0.0f;
            if ((unsigned)gy < 64u && (unsigned)gx < 64u)
                v = src[in_base + (size_t)(ci0 + ci) * chs + gy * 64 + gx];
            sIn[ci][r] = v;
        }
        // --- stage weights ---
        for (int e = tid; e < 8 * 8 * 9; e += 128) {
            int ci  = e / 72;
            int r   = e - ci * 72;
            int co  = r / 9;
            int tap = r - co * 9;
            sW[ci][co][tap] = wts[((size_t)(cog * 8 + co) * CIN + ci0 + ci) * 9 + tap];
        }
        __syncthreads();

#pragma unroll 1
        for (int ci = 0; ci < 8; ci++) {
            float rv[36];                       // 6x6 input patch in registers
#pragma unroll
            for (int yy = 0; yy < 6; yy++)
#pragma unroll
                for (int xx = 0; xx < 6; xx++)
                    rv[yy * 6 + xx] = sIn[ci][(py + yy) * 34 + px + xx];
#pragma unroll
            for (int co = 0; co < 4; co++) {
                float w[9];
#pragma unroll
                for (int tp = 0; tp < 9; tp++) w[tp] = sW[ci][cosub * 4 + co][tp];
#pragma unroll
                for (int dy = 0; dy < 3; dy++)
#pragma unroll
                    for (int dx = 0; dx < 3; dx++)
#pragma unroll
                        for (int iy = 0; iy < 4; iy++)
#pragma unroll
                            for (int ix = 0; ix < 4; ix++)
                                acc[co][iy * 4 + ix] =
                                    fmaf(rv[(iy + dy) * 6 + ix + dx], w[dy * 3 + dx],
                                         acc[co][iy * 4 + ix]);
            }
        }
        __syncthreads();
    }

    // --- epilogue ---
#pragma unroll
    for (int co = 0; co < 4; co++) {
        int c = cog * 8 + cosub * 4 + co;
        float bv = bias[c];
#pragma unroll
        for (int iy = 0; iy < 4; iy++) {
#pragma unroll
            for (int ix = 0; ix < 4; ix++) {
                int pos = (h0 + py + iy) * 64 + (w0 + px + ix);
                float v = acc[co][iy * 4 + ix] + bv;
                if (MODE == 0) {
                    g_XC[((size_t)img * 128 + c) * HW + pos] = v;
                } else if (MODE == 1) {
                    g_yconv[((size_t)b * 96 + c) * HW + pos] = v;
                } else {
                    size_t off = ((size_t)b * 32 + c) * HW + pos;
                    float g2 = g_G2[off];
                    float xy = g_XC[(((size_t)(t * 8 + b)) * 128 + 96 + c) * HW + pos];
                    float yv = g_Y[off];
                    float yn = fmaf(g2, ftanh(xy + v) - yv, yv);   // (1-g2)*Y + g2*tanh(...)
                    g_Y[off] = yn;
                    out[((size_t)(b * 32 + c) * Tn + t) * HW + pos] = yn;
                }
            }
        }
    }
}

// ---------------------------------------------------------------------------
// Elementwise: ms1 gate, Z update, precompute sigmoid gate G2 for Y update.
// ---------------------------------------------------------------------------
__global__ void elemZ_k(int t)
{
    int idx = blockIdx.x * blockDim.x + threadIdx.x;   // over 8*32*4096 = 1M
    if (idx >= 8 * 32 * 4096) return;
    int b   = idx >> 17;            // / (32*4096)
    int rem = idx & 131071;
    int c   = rem >> 12;
    int pos = rem & 4095;

    size_t ybase = ((size_t)b * 96 + c) * HW + pos;
    float yc1 = g_yconv[ybase];
    float yc2 = g_yconv[ybase + 32 * HW];
    float yc3 = g_yconv[ybase + 64 * HW];

    size_t xbase = (((size_t)(t * 8 + b)) * 128 + c) * HW + pos;
    float a1 = g_XC[xbase]            + yc1;   // xg1 + yg1
    float a2 = g_XC[xbase + 32 * HW]  + yc2;   // xg2 + yg2
    float az = g_XC[xbase + 64 * HW]  + yc3;   // xz  + yz

    float ms1 = fsigmoid(a1);                  // DT = 1
    float zv  = g_Z[idx];
    float zn  = fmaf(ms1, ftanh(az) - zv, zv); // (1-ms1)*Z + ms1*tanh(az)
    g_Z[idx]  = zn;
    g_G2[idx] = fsigmoid(a2);
}

__global__ void init_k()
{
    int idx = blockIdx.x * blockDim.x + threadIdx.x;
    if (idx < 8 * 32 * 4096) { g_Y[idx] = 0.0f; g_Z[idx] = 0.0f; }
}

extern "C" void kernel_launch(void* const* d_in, const int* in_sizes, int n_in,
                              void* d_out, int out_size)
{
    const float* X  = (const float*)d_in[0];
    const float* Wx = (const float*)d_in[1];
    const float* bx = (const float*)d_in[2];
    const float* Wy = (const float*)d_in[3];
    const float* by = (const float*)d_in[4];
    const float* Wz = (const float*)d_in[5];
    const float* bz = (const float*)d_in[6];
    float* out = (float*)d_out;

    // Reset recurrent state (graph is replayed; must be deterministic).
    init_k<<<(8 * 32 * 4096 + 255) / 256, 256>>>();

    // Precompute all input convolutions (400 independent images, 128 out ch).
    conv3x3_k<0><<<dim3(4, 16, 400), 128>>>(X, Wx, bx, nullptr, 0);

    // Recurrence: 50 steps, 3 launches each.
    for (int t = 0; t < Tn; t++) {
        conv3x3_k<1><<<dim3(4, 12, 8), 128>>>(nullptr, Wy, by, nullptr, t);
        elemZ_k<<<(8 * 32 * 4096) / 256, 256>>>(t);
        conv3x3_k<2><<<dim3(4, 4, 8), 128>>>(nullptr, Wz, bz, out, t);
    }
}